// round 15
// baseline (speedup 1.0000x reference)
#include <cuda.h>
#include <cuda_runtime.h>

// Warping_65094524339056 — Round 15: R14 (all traffic via TMA) with fixed
// SMEM layout: ddf slice buffers FIRST (128B-aligned TMA destinations),
// image tile second (offset 36864, also 128B-aligned), mbarriers last.
//
// Main loop: 3 conflict-free LDS (ddf) + 8 LDS (gather) + 1 STG. No LDG.
// 1024 threads, VPT=4, 2 blocks/SM = 64 warps.

#define DMASK 127
#define H    4
#define EX   25
#define EY   17
#define EZV  41
#define SZ   44
#define SXY  (EY*SZ)               // 748
#define TILE_ELEMS (EX*SXY)        // 18700 floats = 74800 B
#define NROWS (EX*EY)              // 425
#define TILE_BYTES (TILE_ELEMS*4)
#define DSL_ELEMS 3072             // 96*8*4 floats = 12288 B (128B mult.)
#define DSL_BYTES (DSL_ELEMS*4)
#define DBUF_BYTES (3*DSL_BYTES)   // 36864 B (128B mult.)
#define BLOCK 1024
#define VPT   4

__device__ __forceinline__ float clampf(float v) {
    return fminf(fmaxf(v, 0.0f), 127.0f);
}

__device__ __forceinline__ unsigned smem_u32(const void* p) {
    unsigned a;
    asm("{ .reg .u64 t; cvta.to.shared.u64 t, %1; cvt.u32.u64 %0, t; }"
        : "=r"(a) : "l"(p));
    return a;
}

#define MBAR_WAIT(addr, par)                                        \
    asm volatile(                                                   \
        "{\n\t.reg .pred P;\n\t"                                    \
        "W_%=:\n\t"                                                 \
        "mbarrier.try_wait.parity.shared.b64 P, [%0], %1;\n\t"      \
        "@!P bra W_%=;\n\t}"                                        \
        :: "r"(addr), "r"(par) : "memory")

__global__ __launch_bounds__(BLOCK, 2) void warp_kernel(
    const float* __restrict__ ddf,
    const float* __restrict__ image,
    float* __restrict__ out,
    const __grid_constant__ CUtensorMap img_desc,
    const __grid_constant__ CUtensorMap ddf_desc)
{
    extern __shared__ float smem[];
    float* dbuf = smem;                          // 3 x 3072 floats (offset 0)
    float* tile = smem + 3 * DSL_ELEMS;          // 18700 floats (offset 36864)

    unsigned sbase = smem_u32(smem);
    unsigned dbase = sbase;                      // 128B aligned
    unsigned tbase = sbase + DBUF_BYTES;         // 36864: 128B aligned
    unsigned mb    = tbase + TILE_BYTES;         // 8B aligned (74800%8==0)
    unsigned mb_img   = mb;
    unsigned mb_full0 = mb + 8;     // ddf slots 0..2 at +8,+16,+24
    unsigned mb_empty = mb + 32;

    int tid = threadIdx.x;
    int bid = blockIdx.x;
    // 8(x) x 16(y) x 4(z) tiles x 4 batches = 2048 blocks
    int tz = bid & 3;
    int ty = (bid >> 2) & 15;
    int tx = (bid >> 6) & 7;
    int b  = bid >> 9;

    int X0 = tx << 4;
    int Y0 = ty << 3;
    int Z0 = tz << 5;

    const float* img = image + ((long long)b << 21);

    // ---- per-thread compute coords ----
    int lz  = tid & 31;
    int ly  = (tid >> 5) & 7;
    int lxh = tid >> 8;                // 0..3; x = X0 + 4*v + lxh
    int y = Y0 + ly;
    int z = Z0 + lz;

    float* outb = out + ((long long)b << 21);
    int vid0 = ((X0 + lxh) << 14) + (y << 7) + z;
    int dIdx = ((lxh << 3) + ly) * 96 + lz * 3;   // within-slice ddf index

    if (tid == 0) {
        asm volatile("mbarrier.init.shared.b64 [%0], %1;" :: "r"(mb_img),       "r"(1u)  : "memory");
        asm volatile("mbarrier.init.shared.b64 [%0], %1;" :: "r"(mb_full0),     "r"(1u)  : "memory");
        asm volatile("mbarrier.init.shared.b64 [%0], %1;" :: "r"(mb_full0+8u),  "r"(1u)  : "memory");
        asm volatile("mbarrier.init.shared.b64 [%0], %1;" :: "r"(mb_full0+16u), "r"(1u)  : "memory");
        asm volatile("mbarrier.init.shared.b64 [%0], %1;" :: "r"(mb_empty),     "r"(32u) : "memory");
    }
    __syncthreads();

    if (tid == 0) {
        // image tile
        asm volatile("mbarrier.arrive.expect_tx.shared.b64 _, [%0], %1;"
                     :: "r"(mb_img), "r"((unsigned)TILE_BYTES) : "memory");
        asm volatile(
            "cp.async.bulk.tensor.4d.shared::cta.global.tile.mbarrier::complete_tx::bytes "
            "[%0], [%1, {%2, %3, %4, %5}], [%6];"
            :: "r"(tbase), "l"(&img_desc),
               "r"(Z0 - H), "r"(Y0 - H), "r"(X0 - H), "r"(b), "r"(mb_img)
            : "memory");
        // ddf slices 0..2
#pragma unroll
        for (int s = 0; s < 3; s++) {
            asm volatile("mbarrier.arrive.expect_tx.shared.b64 _, [%0], %1;"
                         :: "r"(mb_full0 + 8u * s), "r"((unsigned)DSL_BYTES) : "memory");
            asm volatile(
                "cp.async.bulk.tensor.4d.shared::cta.global.tile.mbarrier::complete_tx::bytes "
                "[%0], [%1, {%2, %3, %4, %5}], [%6];"
                :: "r"(dbase + s * (unsigned)DSL_BYTES), "l"(&ddf_desc),
                   "r"(Z0 * 3), "r"(Y0), "r"(X0 + 4 * s), "r"(b),
                   "r"(mb_full0 + 8u * s)
                : "memory");
        }
    }

    // ---- wait image tile, then border fixups ----
    MBAR_WAIT(mb_img, 0u);

    if (tx == 0) {
        for (int i = tid; i < 4 * SXY; i += BLOCK)
            tile[i] = tile[4 * SXY + (i % SXY)];
        __syncthreads();
    } else if (tx == 7) {
        for (int i = tid; i < 5 * SXY; i += BLOCK)
            tile[20 * SXY + i] = tile[19 * SXY + (i % SXY)];
        __syncthreads();
    }
    if (ty == 0) {
        for (int i = tid; i < EX * 4 * SZ; i += BLOCK) {
            int sx  = i / (4 * SZ);
            int rem = i - sx * (4 * SZ);
            tile[sx * SXY + rem] = tile[sx * SXY + 4 * SZ + (rem % SZ)];
        }
        __syncthreads();
    } else if (ty == 15) {
        for (int i = tid; i < EX * 5 * SZ; i += BLOCK) {
            int sx  = i / (5 * SZ);
            int rem = i - sx * (5 * SZ);
            tile[sx * SXY + 12 * SZ + rem] = tile[sx * SXY + 11 * SZ + (rem % SZ)];
        }
        __syncthreads();
    }
    if (tz == 0) {
        for (int r = tid; r < NROWS; r += BLOCK) {
            float v = tile[r * SZ + 4];
            tile[r * SZ + 0] = v;  tile[r * SZ + 1] = v;
            tile[r * SZ + 2] = v;  tile[r * SZ + 3] = v;
        }
        __syncthreads();
    } else if (tz == 3) {
        for (int r = tid; r < NROWS; r += BLOCK) {
            float v = tile[r * SZ + 35];
            tile[r * SZ + 36] = v;  tile[r * SZ + 37] = v;
            tile[r * SZ + 38] = v;  tile[r * SZ + 39] = v;
            tile[r * SZ + 40] = v;
        }
        __syncthreads();
    }

    const float yf = (float)y;
    const float zf = (float)z;
    const int ox = X0 - H, oy = Y0 - H, oz = Z0 - H;

#pragma unroll
    for (int v = 0; v < VPT; v++) {
        int slot  = (v < 3) ? v : 0;
        unsigned par = (v < 3) ? 0u : 1u;

        MBAR_WAIT(mb_full0 + 8u * slot, par);

        const float* dsl = dbuf + slot * DSL_ELEMS;
        float dx = dsl[dIdx];
        float dy = dsl[dIdx + 1];
        float dz = dsl[dIdx + 2];

        int x = X0 + 4 * v + lxh;
        int vid = vid0 + (v << 16);        // x += 4 per iter

        float fx = (float)x + dx;          // same fp as reference
        float fy = yf + dy;
        float fz = zf + dz;

        int ix0 = __float2int_rd(fx);
        int iy0 = __float2int_rd(fy);
        int iz0 = __float2int_rd(fz);
        float wx = fx - (float)ix0;
        float wy = fy - (float)iy0;
        float wz = fz - (float)iz0;

        int sx0 = ix0 - ox;
        int sy0 = iy0 - oy;
        int sz0 = iz0 - oz;

        bool okk = ((unsigned)sx0 <= (unsigned)(EX - 2)) &
                   ((unsigned)sy0 <= (unsigned)(EY - 2)) &
                   ((unsigned)sz0 <= (unsigned)(EZV - 2));

        float v000, v001, v010, v011, v100, v101, v110, v111;
        if (okk) {
            int base = (sx0 * EY + sy0) * SZ + sz0;
            v000 = tile[base];
            v001 = tile[base + 1];
            v010 = tile[base + SZ];
            v011 = tile[base + SZ + 1];
            v100 = tile[base + SXY];
            v101 = tile[base + SXY + 1];
            v110 = tile[base + SXY + SZ];
            v111 = tile[base + SXY + SZ + 1];
        } else {
            // rare: beyond halo -> clamped global gather (matches reference)
            float cfx = clampf(fx), cfy = clampf(fy), cfz = clampf(fz);
            ix0 = (int)cfx;  iy0 = (int)cfy;  iz0 = (int)cfz;
            wx = cfx - (float)ix0;
            wy = cfy - (float)iy0;
            wz = cfz - (float)iz0;
            int ix1 = min(ix0 + 1, DMASK);
            int iy1 = min(iy0 + 1, DMASK);
            int iz1 = min(iz0 + 1, DMASK);
            int g00 = (ix0 << 14) + (iy0 << 7);
            int g01 = (ix0 << 14) + (iy1 << 7);
            int g10 = (ix1 << 14) + (iy0 << 7);
            int g11 = (ix1 << 14) + (iy1 << 7);
            v000 = __ldg(img + g00 + iz0);  v001 = __ldg(img + g00 + iz1);
            v010 = __ldg(img + g01 + iz0);  v011 = __ldg(img + g01 + iz1);
            v100 = __ldg(img + g10 + iz0);  v101 = __ldg(img + g10 + iz1);
            v110 = __ldg(img + g11 + iz0);  v111 = __ldg(img + g11 + iz1);
        }

        float c00 = v000 + wz * (v001 - v000);
        float c01 = v010 + wz * (v011 - v010);
        float c10 = v100 + wz * (v101 - v100);
        float c11 = v110 + wz * (v111 - v110);
        float c0  = c00 + wy * (c01 - c00);
        float c1  = c10 + wy * (c11 - c10);
        __stcs(&outb[vid], c0 + wx * (c1 - c0));

        // after iter 0: free slot 0 and reissue slice 3 into it
        if (v == 0) {
            if ((tid & 31) == 0) {
                asm volatile("mbarrier.arrive.shared.b64 _, [%0];"
                             :: "r"(mb_empty) : "memory");
            }
            if (tid == 0) {
                MBAR_WAIT(mb_empty, 0u);
                asm volatile("mbarrier.arrive.expect_tx.shared.b64 _, [%0], %1;"
                             :: "r"(mb_full0), "r"((unsigned)DSL_BYTES) : "memory");
                asm volatile(
                    "cp.async.bulk.tensor.4d.shared::cta.global.tile.mbarrier::complete_tx::bytes "
                    "[%0], [%1, {%2, %3, %4, %5}], [%6];"
                    :: "r"(dbase), "l"(&ddf_desc),
                       "r"(Z0 * 3), "r"(Y0), "r"(X0 + 12), "r"(b), "r"(mb_full0)
                    : "memory");
            }
        }
    }
}

typedef CUresult (*EncodeTiledFn)(
    CUtensorMap*, CUtensorMapDataType, cuuint32_t, void*,
    const cuuint64_t*, const cuuint64_t*, const cuuint32_t*, const cuuint32_t*,
    CUtensorMapInterleave, CUtensorMapSwizzle, CUtensorMapL2promotion,
    CUtensorMapFloatOOBfill);

extern "C" void kernel_launch(void* const* d_in, const int* in_sizes, int n_in,
                              void* d_out, int out_size)
{
    const float* ddf   = (const float*)d_in[0];
    const float* image = (const float*)d_in[1];
    float* out = (float*)d_out;

    void* fp = nullptr;
    cudaDriverEntryPointQueryResult qres;
    cudaGetDriverEntryPoint("cuTensorMapEncodeTiled", &fp,
                            cudaEnableDefault, &qres);
    EncodeTiledFn encode = (EncodeTiledFn)fp;

    // image map: (z=128, y=128, x=128, b=4), box (44,17,25,1)
    CUtensorMap img_desc;
    {
        cuuint64_t dims[4]    = {128, 128, 128, 4};
        cuuint64_t strides[3] = {128ull * 4, 128ull * 128 * 4,
                                 128ull * 128 * 128 * 4};
        cuuint32_t box[4]     = {SZ, EY, EX, 1};
        cuuint32_t estr[4]    = {1, 1, 1, 1};
        encode(&img_desc, CU_TENSOR_MAP_DATA_TYPE_FLOAT32, 4, (void*)image,
               dims, strides, box, estr,
               CU_TENSOR_MAP_INTERLEAVE_NONE, CU_TENSOR_MAP_SWIZZLE_NONE,
               CU_TENSOR_MAP_L2_PROMOTION_L2_128B,
               CU_TENSOR_MAP_FLOAT_OOB_FILL_NONE);
    }

    // ddf map: (zc=384, y=128, x=128, b=4), box (96,8,4,1)
    CUtensorMap ddf_desc;
    {
        cuuint64_t dims[4]    = {384, 128, 128, 4};
        cuuint64_t strides[3] = {384ull * 4, 384ull * 128 * 4,
                                 384ull * 128 * 128 * 4};
        cuuint32_t box[4]     = {96, 8, 4, 1};
        cuuint32_t estr[4]    = {1, 1, 1, 1};
        encode(&ddf_desc, CU_TENSOR_MAP_DATA_TYPE_FLOAT32, 4, (void*)ddf,
               dims, strides, box, estr,
               CU_TENSOR_MAP_INTERLEAVE_NONE, CU_TENSOR_MAP_SWIZZLE_NONE,
               CU_TENSOR_MAP_L2_PROMOTION_L2_128B,
               CU_TENSOR_MAP_FLOAT_OOB_FILL_NONE);
    }

    size_t smem = DBUF_BYTES + TILE_BYTES + 48;   // 111712 B
    cudaFuncSetAttribute(warp_kernel,
                         cudaFuncAttributeMaxDynamicSharedMemorySize, (int)smem);

    warp_kernel<<<2048, BLOCK, smem>>>(ddf, image, out, img_desc, ddf_desc);
}

// round 16
// speedup vs baseline: 1.0007x; 1.0007x over previous
#include <cuda.h>
#include <cuda_runtime.h>

// Warping_65094524339056 — Round 16: R12 (TMA tile) + explicit 2-stage
// software pipeline (issue iteration v+1's 8 gather LDS before iteration v's
// FMA tree) at a 64-reg budget. Three ddf variants all hit ~44us with every
// pipe at 50-65% -> latency-bound on the LDS->FMA chain; this buys overlap.

#define DMASK 127
#define H    4
#define EX   25
#define EY   17
#define EZV  41
#define SZ   44
#define SXY  (EY*SZ)               // 748
#define TILE_ELEMS (EX*SXY)        // 18700 floats = 74800 B
#define NROWS (EX*EY)              // 425
#define TILE_BYTES (TILE_ELEMS*4)
#define BLOCK 512
#define VPT   8
#define PF    4                    // ddf ring depth

__device__ __forceinline__ float clampf(float v) {
    return fminf(fmaxf(v, 0.0f), 127.0f);
}

__device__ __forceinline__ unsigned smem_u32(const void* p) {
    unsigned a;
    asm("{ .reg .u64 t; cvta.to.shared.u64 t, %1; cvt.u32.u64 %0, t; }"
        : "=r"(a) : "l"(p));
    return a;
}

#define MBAR_WAIT(addr, par)                                        \
    asm volatile(                                                   \
        "{\n\t.reg .pred P;\n\t"                                    \
        "W_%=:\n\t"                                                 \
        "mbarrier.try_wait.parity.shared.b64 P, [%0], %1;\n\t"      \
        "@!P bra W_%=;\n\t}"                                        \
        :: "r"(addr), "r"(par) : "memory")

__global__ __launch_bounds__(BLOCK, 2) void warp_kernel(
    const float* __restrict__ ddf,
    const float* __restrict__ image,
    float* __restrict__ out,
    const __grid_constant__ CUtensorMap desc)
{
    extern __shared__ float tile[];
    unsigned sbase = smem_u32(tile);
    unsigned mbar  = sbase + TILE_BYTES;

    int tid = threadIdx.x;
    int bid = blockIdx.x;
    // 8(x) x 16(y) x 4(z) tiles x 4 batches = 2048 blocks
    int tz = bid & 3;
    int ty = (bid >> 2) & 15;
    int tx = (bid >> 6) & 7;
    int b  = bid >> 9;

    int X0 = tx << 4;
    int Y0 = ty << 3;
    int Z0 = tz << 5;

    const float* img = image + ((long long)b << 21);

    // ---- per-thread compute coords ----
    int lz  = tid & 31;
    int ly  = (tid >> 5) & 7;
    int lxh = tid >> 8;                // 0/1; x = X0 + lxh + 2*v
    int y = Y0 + ly;
    int z = Z0 + lz;
    int xb = X0 + lxh;

    int vid0 = (xb << 14) + (y << 7) + z;
    const float* ddfb = ddf + ((long long)b << 21) * 3;
    float*       outb = out + ((long long)b << 21);
    const float* dp0  = ddfb + (long long)vid0 * 3;
    const int DSTRIDE = 3 << 15;

    if (tid == 0) {
        asm volatile("mbarrier.init.shared.b64 [%0], %1;"
                     :: "r"(mbar), "r"(1u) : "memory");
    }

    // ---- ddf prefetch ring (depth 4): in flight while TMA runs ----
    float rdx[PF], rdy[PF], rdz[PF];
#pragma unroll
    for (int p = 0; p < PF; p++) {
        const float* pp = dp0 + p * DSTRIDE;
        rdx[p] = __ldcs(pp);
        rdy[p] = __ldcs(pp + 1);
        rdz[p] = __ldcs(pp + 2);
    }

    __syncthreads();   // mbarrier init visible

    if (tid == 0) {
        asm volatile("mbarrier.arrive.expect_tx.shared.b64 _, [%0], %1;"
                     :: "r"(mbar), "r"((unsigned)TILE_BYTES) : "memory");
        asm volatile(
            "cp.async.bulk.tensor.4d.shared::cta.global.tile.mbarrier::complete_tx::bytes "
            "[%0], [%1, {%2, %3, %4, %5}], [%6];"
            :: "r"(sbase), "l"(&desc),
               "r"(Z0 - H), "r"(Y0 - H), "r"(X0 - H), "r"(b), "r"(mbar)
            : "memory");
    }

    MBAR_WAIT(mbar, 0u);

    // ---- border fixups (block-uniform; x -> y -> z propagates corners) ----
    if (tx == 0) {
        for (int i = tid; i < 4 * SXY; i += BLOCK)
            tile[i] = tile[4 * SXY + (i % SXY)];
        __syncthreads();
    } else if (tx == 7) {
        for (int i = tid; i < 5 * SXY; i += BLOCK)
            tile[20 * SXY + i] = tile[19 * SXY + (i % SXY)];
        __syncthreads();
    }
    if (ty == 0) {
        for (int i = tid; i < EX * 4 * SZ; i += BLOCK) {
            int sx  = i / (4 * SZ);
            int rem = i - sx * (4 * SZ);
            tile[sx * SXY + rem] = tile[sx * SXY + 4 * SZ + (rem % SZ)];
        }
        __syncthreads();
    } else if (ty == 15) {
        for (int i = tid; i < EX * 5 * SZ; i += BLOCK) {
            int sx  = i / (5 * SZ);
            int rem = i - sx * (5 * SZ);
            tile[sx * SXY + 12 * SZ + rem] = tile[sx * SXY + 11 * SZ + (rem % SZ)];
        }
        __syncthreads();
    }
    if (tz == 0) {
        for (int r = tid; r < NROWS; r += BLOCK) {
            float v = tile[r * SZ + 4];
            tile[r * SZ + 0] = v;  tile[r * SZ + 1] = v;
            tile[r * SZ + 2] = v;  tile[r * SZ + 3] = v;
        }
        __syncthreads();
    } else if (tz == 3) {
        for (int r = tid; r < NROWS; r += BLOCK) {
            float v = tile[r * SZ + 35];
            tile[r * SZ + 36] = v;  tile[r * SZ + 37] = v;
            tile[r * SZ + 38] = v;  tile[r * SZ + 39] = v;
            tile[r * SZ + 40] = v;
        }
        __syncthreads();
    }

    const float yf = (float)y;
    const float zf = (float)z;
    const int ox = X0 - H, oy = Y0 - H, oz = Z0 - H;

    // ---- stage A: ddf ring consume + coords + gather (LDS or fallback) ----
    auto stageA = [&](int v, float* g, float& wx, float& wy, float& wz) {
        int slot = v % PF;
        float dx = rdx[slot], dy = rdy[slot], dz = rdz[slot];
        if (v + PF < VPT) {
            const float* pn = dp0 + (v + PF) * DSTRIDE;
            rdx[slot] = __ldcs(pn);
            rdy[slot] = __ldcs(pn + 1);
            rdz[slot] = __ldcs(pn + 2);
        }

        float fx = (float)(xb + 2 * v) + dx;     // same fp as reference
        float fy = yf + dy;
        float fz = zf + dz;

        int ix0 = __float2int_rd(fx);
        int iy0 = __float2int_rd(fy);
        int iz0 = __float2int_rd(fz);
        wx = fx - (float)ix0;
        wy = fy - (float)iy0;
        wz = fz - (float)iz0;

        int sx0 = ix0 - ox;
        int sy0 = iy0 - oy;
        int sz0 = iz0 - oz;

        bool okk = ((unsigned)sx0 <= (unsigned)(EX - 2)) &
                   ((unsigned)sy0 <= (unsigned)(EY - 2)) &
                   ((unsigned)sz0 <= (unsigned)(EZV - 2));

        if (okk) {
            int base = (sx0 * EY + sy0) * SZ + sz0;
            g[0] = tile[base];
            g[1] = tile[base + 1];
            g[2] = tile[base + SZ];
            g[3] = tile[base + SZ + 1];
            g[4] = tile[base + SXY];
            g[5] = tile[base + SXY + 1];
            g[6] = tile[base + SXY + SZ];
            g[7] = tile[base + SXY + SZ + 1];
        } else {
            // rare: beyond halo -> clamped global gather (matches reference)
            float cfx = clampf(fx), cfy = clampf(fy), cfz = clampf(fz);
            ix0 = (int)cfx;  iy0 = (int)cfy;  iz0 = (int)cfz;
            wx = cfx - (float)ix0;
            wy = cfy - (float)iy0;
            wz = cfz - (float)iz0;
            int ix1 = min(ix0 + 1, DMASK);
            int iy1 = min(iy0 + 1, DMASK);
            int iz1 = min(iz0 + 1, DMASK);
            int g00 = (ix0 << 14) + (iy0 << 7);
            int g01 = (ix0 << 14) + (iy1 << 7);
            int g10 = (ix1 << 14) + (iy0 << 7);
            int g11 = (ix1 << 14) + (iy1 << 7);
            g[0] = __ldg(img + g00 + iz0);  g[1] = __ldg(img + g00 + iz1);
            g[2] = __ldg(img + g01 + iz0);  g[3] = __ldg(img + g01 + iz1);
            g[4] = __ldg(img + g10 + iz0);  g[5] = __ldg(img + g10 + iz1);
            g[6] = __ldg(img + g11 + iz0);  g[7] = __ldg(img + g11 + iz1);
        }
    };

    // ---- stage B: FMA tree + store ----
    auto stageB = [&](int v, const float* g, float wx, float wy, float wz) {
        float c00 = g[0] + wz * (g[1] - g[0]);
        float c01 = g[2] + wz * (g[3] - g[2]);
        float c10 = g[4] + wz * (g[5] - g[4]);
        float c11 = g[6] + wz * (g[7] - g[6]);
        float c0  = c00 + wy * (c01 - c00);
        float c1  = c10 + wy * (c11 - c10);
        __stcs(&outb[vid0 + (v << 15)], c0 + wx * (c1 - c0));
    };

    // ---- pipelined main loop: A(v+1) issued before B(v) consumes ----
    float gA[8], gB[8];
    float wxA, wyA, wzA, wxB, wyB, wzB;

    stageA(0, gA, wxA, wyA, wzA);
#pragma unroll
    for (int v = 0; v < VPT; v++) {
        if (v & 1) {
            if (v + 1 < VPT) stageA(v + 1, gA, wxA, wyA, wzA);
            stageB(v, gB, wxB, wyB, wzB);
        } else {
            if (v + 1 < VPT) stageA(v + 1, gB, wxB, wyB, wzB);
            stageB(v, gA, wxA, wyA, wzA);
        }
    }
}

typedef CUresult (*EncodeTiledFn)(
    CUtensorMap*, CUtensorMapDataType, cuuint32_t, void*,
    const cuuint64_t*, const cuuint64_t*, const cuuint32_t*, const cuuint32_t*,
    CUtensorMapInterleave, CUtensorMapSwizzle, CUtensorMapL2promotion,
    CUtensorMapFloatOOBfill);

extern "C" void kernel_launch(void* const* d_in, const int* in_sizes, int n_in,
                              void* d_out, int out_size)
{
    const float* ddf   = (const float*)d_in[0];
    const float* image = (const float*)d_in[1];
    float* out = (float*)d_out;

    void* fp = nullptr;
    cudaDriverEntryPointQueryResult qres;
    cudaGetDriverEntryPoint("cuTensorMapEncodeTiled", &fp,
                            cudaEnableDefault, &qres);
    EncodeTiledFn encode = (EncodeTiledFn)fp;

    CUtensorMap desc;
    cuuint64_t dims[4]    = {128, 128, 128, 4};
    cuuint64_t strides[3] = {128ull * 4, 128ull * 128 * 4,
                             128ull * 128 * 128 * 4};
    cuuint32_t box[4]     = {SZ, EY, EX, 1};
    cuuint32_t estr[4]    = {1, 1, 1, 1};
    encode(&desc, CU_TENSOR_MAP_DATA_TYPE_FLOAT32, 4, (void*)image,
           dims, strides, box, estr,
           CU_TENSOR_MAP_INTERLEAVE_NONE, CU_TENSOR_MAP_SWIZZLE_NONE,
           CU_TENSOR_MAP_L2_PROMOTION_L2_128B,
           CU_TENSOR_MAP_FLOAT_OOB_FILL_NONE);

    size_t smem = TILE_BYTES + 16;
    cudaFuncSetAttribute(warp_kernel,
                         cudaFuncAttributeMaxDynamicSharedMemorySize, (int)smem);

    warp_kernel<<<2048, BLOCK, smem>>>(ddf, image, out, desc);
}